// round 2
// baseline (speedup 1.0000x reference)
#include <cuda_runtime.h>

// BinsChamferLoss: 1-D bidirectional chamfer between bin centers and depth pixels.
// Shapes (fixed by the problem): bins [L=4, N=4, 257] f32, depth [N=4, 240, 320] f32.
// Output: scalar f32 loss.
//
// Algorithm (exact, no brute force):
//   k_prep : centers = midpoints of adjacent bin edges; bitonic-sort each of the
//            16 (l,n) lists of 256; re-init all accumulators (graph-replay safe).
//   k_main : per valid pixel y, per scale: branchless binary search over sorted
//            centers -> nearest-center dist^2 (cham_y sum) AND segment index j.
//            Update per-segment max/min of y via uint-bit-pattern REDG atomics.
//            Count valid pixels per batch.
//   k_final: per (l,n): prefix-max over segMax and suffix-min over segMin give,
//            for each center, the nearest valid y on each side -> cham_x.
//            Combine: loss = sum_l mean_n (cham_x + cham_y).

#define LSC 4
#define NB  4
#define P   256
#define P1  257
#define M   76800
#define LNN 16
#define CPB 75       // chunks per batch
#define CHUNK 1024   // pixels per block (CPB*CHUNK == M)

__device__ float    g_sortedC[LNN][P];
__device__ unsigned g_segMax[LNN][P1];   // uint bit pattern of max valid y per segment (0 = empty)
__device__ unsigned g_segMin[LNN][P1];   // uint bit pattern of min valid y per segment (+inf = empty)
__device__ float    g_sumY[LNN];         // sum over valid y of nearest-center dist^2
__device__ unsigned g_cnt[NB];           // valid-pixel count per batch

__global__ void k_prep(const float* __restrict__ bins)
{
    const int ln = blockIdx.x;        // ln = l*NB + n, matches bins[l][n] layout
    const int t  = threadIdx.x;
    __shared__ float s[P];

    const float* e = bins + ln * P1;
    s[t] = 0.5f * (e[t] + e[t + 1]);

    // re-init accumulators every launch (graph replays)
    g_segMax[ln][t] = 0u;
    g_segMin[ln][t] = 0x7F800000u;
    if (t == 0) {
        g_segMax[ln][P] = 0u;
        g_segMin[ln][P] = 0x7F800000u;
        g_sumY[ln] = 0.f;
        if (ln < NB) g_cnt[ln] = 0u;
    }
    __syncthreads();

    // bitonic sort, 256 elements, 256 threads, ascending
    for (int k = 2; k <= P; k <<= 1) {
        for (int j = k >> 1; j > 0; j >>= 1) {
            int ixj = t ^ j;
            if (ixj > t) {
                float a = s[t], b = s[ixj];
                bool asc = ((t & k) == 0);
                if ((a > b) == asc) { s[t] = b; s[ixj] = a; }
            }
            __syncthreads();
        }
    }
    g_sortedC[ln][t] = s[t];
}

__global__ void k_main(const float* __restrict__ depth)
{
    __shared__ float sc[LSC][P];
    const int n     = blockIdx.x / CPB;
    const int chunk = blockIdx.x % CPB;
    const int t     = threadIdx.x;

    for (int k = t; k < LSC * P; k += blockDim.x) {
        int l = k >> 8, i = k & 255;
        sc[l][i] = g_sortedC[l * NB + n][i];
    }
    __syncthreads();

    const float* y0 = depth + n * M + chunk * CHUNK;
    float sums[LSC] = {0.f, 0.f, 0.f, 0.f};
    unsigned cnt = 0;

    #pragma unroll
    for (int it = 0; it < CHUNK / 256; ++it) {
        float y = y0[it * 256 + t];
        if (y >= 0.001f) {
            cnt++;
            unsigned uy = __float_as_uint(y);
            #pragma unroll
            for (int l = 0; l < LSC; l++) {
                const float* c = sc[l];
                // branchless upper-bound: j = count of centers <= y, j in [0,256]
                int j = 0;
                #pragma unroll
                for (int st = 256; st > 0; st >>= 1)
                    if (j + st <= P && c[j + st - 1] <= y) j += st;
                float dl = (j > 0) ? (y - c[j - 1]) : 1e18f;
                float dr = (j < P) ? (c[j] - y)     : 1e18f;
                sums[l] += fminf(dl * dl, dr * dr);
                int ln = l * NB + n;
                atomicMax(&g_segMax[ln][j], uy);   // nonneg float: uint order == float order
                atomicMin(&g_segMin[ln][j], uy);
            }
        }
    }

    // warp reduce, then one global atomic per warp per accumulator
    #pragma unroll
    for (int off = 16; off; off >>= 1) {
        #pragma unroll
        for (int l = 0; l < LSC; l++)
            sums[l] += __shfl_down_sync(0xffffffffu, sums[l], off);
        cnt += __shfl_down_sync(0xffffffffu, cnt, off);
    }
    if ((t & 31) == 0) {
        #pragma unroll
        for (int l = 0; l < LSC; l++)
            atomicAdd(&g_sumY[l * NB + n], sums[l]);
        atomicAdd(&g_cnt[n], cnt);
    }
}

__global__ void k_final(float* __restrict__ out)
{
    __shared__ float sMax[LNN][P1];
    __shared__ float sMin[LNN][P1];
    __shared__ float chamx[LNN];
    const int t = threadIdx.x;   // 512 threads

    for (int k = t; k < LNN * P1; k += 512) {
        int ln = k / P1, i = k % P1;
        unsigned u = g_segMax[ln][i];
        sMax[ln][i] = (u == 0u) ? -1e30f : __uint_as_float(u);
        sMin[ln][i] = __uint_as_float(g_segMin[ln][i]);   // +inf when empty
    }
    __syncthreads();

    if (t < LNN) {
        float rM = -1e30f;
        for (int i = 0; i < P1; i++) { rM = fmaxf(rM, sMax[t][i]); sMax[t][i] = rM; }
        float rm = __uint_as_float(0x7F800000u);
        for (int i = P1 - 1; i >= 0; i--) { rm = fminf(rm, sMin[t][i]); sMin[t][i] = rm; }
    }
    __syncthreads();

    // warp w handles (l,n)=w; lane covers 8 centers
    const int w = t >> 5, lane = t & 31;
    float s = 0.f;
    #pragma unroll
    for (int cb = 0; cb < P / 32; cb++) {
        int i = cb * 32 + lane;
        float c  = g_sortedC[w][i];
        float dl = c - sMax[w][i];        // nearest valid y below c[i] (or -1e30 -> inf^2)
        float dr = sMin[w][i + 1] - c;    // nearest valid y at/above c[i]
        s += fminf(dl * dl, dr * dr);
    }
    #pragma unroll
    for (int off = 16; off; off >>= 1)
        s += __shfl_down_sync(0xffffffffu, s, off);
    if (lane == 0) chamx[w] = s * (1.f / P);
    __syncthreads();

    if (t == 0) {
        float loss = 0.f;
        for (int ln = 0; ln < LNN; ln++) {
            int n = ln & 3;   // ln = l*NB + n
            loss += chamx[ln] + g_sumY[ln] / (float)g_cnt[n];
        }
        out[0] = loss * (1.f / NB);   // mean over batch, summed over scales
    }
}

extern "C" void kernel_launch(void* const* d_in, const int* in_sizes, int n_in,
                              void* d_out, int out_size)
{
    const float* bins  = (const float*)d_in[0];
    const float* depth = (const float*)d_in[1];
    float* out = (float*)d_out;

    k_prep <<<LNN, P>>>(bins);
    k_main <<<NB * CPB, 256>>>(depth);
    k_final<<<1, 512>>>(out);
}

// round 3
// speedup vs baseline: 1.4800x; 1.4800x over previous
#include <cuda_runtime.h>

// BinsChamferLoss: exact 1-D bidirectional chamfer.
// bins [L=4, N=4, 257] f32, depth [N=4, 240, 320] f32 -> scalar f32.
//
// k_prep : centers, hybrid shfl/smem bitonic sort (16 lists of 256),
//          1024-bucket direct-answer LUT per list, accumulator re-init.
// k_main : per valid pixel: bucket -> LUT -> (usually) direct {j, c[j-1], c[j]};
//          cham_y sum in registers; per-segment y max/min aggregated in SMEM
//          atomics, flushed to global once per block. Last block (g_done
//          ticket) runs the finalize: warp-parallel prefix-max / suffix-min
//          over 257 segments per (l,n) -> cham_x, combine, write out.

#define LSC 4
#define NB  4
#define P   256
#define P1  257
#define M   76800
#define LNN 16
#define NBUCK 1024
#define BPB 30            // blocks per batch
#define GRID (NB*BPB)     // 120
#define PPB (M/BPB)       // 2560 pixels per block
#define PPT (PPB/256)     // 10 pixels per thread

__device__ float    g_sortedC[LNN][P];
__device__ float4   g_lut[LNN * NBUCK];     // {cl, cr, j0(bits), j1(bits)}
__device__ unsigned g_segMax[LNN][P1];
__device__ unsigned g_segMin[LNN][P1];
__device__ float    g_sumY[LNN];
__device__ unsigned g_cnt[NB];
__device__ unsigned g_done;

__global__ void k_prep(const float* __restrict__ bins)
{
    const int ln = blockIdx.x;
    const int t  = threadIdx.x;
    __shared__ float s[P];

    const float* e = bins + ln * P1;
    float v = 0.5f * (e[t] + e[t + 1]);

    // re-init accumulators (graph replay safe)
    g_segMax[ln][t] = 0u;
    g_segMin[ln][t] = 0x7F800000u;
    if (t == 0) {
        g_segMax[ln][P] = 0u;
        g_segMin[ln][P] = 0x7F800000u;
        g_sumY[ln] = 0.f;
        if (ln < NB) g_cnt[ln] = 0u;
        if (ln == 0) g_done = 0u;
    }

    // bitonic sort: shfl for j<32, smem for j>=32
    #pragma unroll
    for (int k = 2; k <= P; k <<= 1) {
        #pragma unroll
        for (int j = k >> 1; j > 0; j >>= 1) {
            bool asc   = ((t & k) == 0);
            bool lower = ((t & j) == 0);
            float pv;
            if (j < 32) {
                pv = __shfl_xor_sync(0xffffffffu, v, j);
            } else {
                __syncthreads();
                s[t] = v;
                __syncthreads();
                pv = s[t ^ j];
            }
            v = (lower == asc) ? fminf(v, pv) : fmaxf(v, pv);
        }
    }
    __syncthreads();
    s[t] = v;
    g_sortedC[ln][t] = v;
    __syncthreads();

    // LUT: 4 buckets per thread
    #pragma unroll
    for (int q = 0; q < NBUCK / 256; q++) {
        int b = t + q * 256;
        float lo = (float)b * (1.f / NBUCK);        // exact (pow2)
        float hi = (float)(b + 1) * (1.f / NBUCK);
        // j0 = #centers <= lo ; j1 = #centers < hi
        int j0 = 0, j1 = 0;
        #pragma unroll
        for (int st = 256; st > 0; st >>= 1) {
            if (j0 + st <= P && s[j0 + st - 1] <= lo) j0 += st;
            if (j1 + st <= P && s[j1 + st - 1] <  hi) j1 += st;
        }
        float cl = (j0 > 0) ? s[j0 - 1] : -1e18f;
        float cr = (j0 < P) ? s[j0]     :  1e18f;
        g_lut[ln * NBUCK + b] =
            make_float4(cl, cr, __uint_as_float((unsigned)j0),
                                __uint_as_float((unsigned)j1));
    }
}

__global__ void __launch_bounds__(256) k_main(const float* __restrict__ depth,
                                              float* __restrict__ out)
{
    __shared__ unsigned sMax[LSC][P1];   // per-block segment aggregation
    __shared__ unsigned sMin[LSC][P1];
    __shared__ float    chamx[LNN];
    __shared__ int      sLast;

    const int n  = blockIdx.x / BPB;
    const int cb = blockIdx.x % BPB;
    const int t  = threadIdx.x;
    const int lane = t & 31;
    const int w    = t >> 5;

    for (int k = t; k < LSC * P1; k += 256) {
        ((unsigned*)sMax)[k] = 0u;
        ((unsigned*)sMin)[k] = 0x7F800000u;
    }
    __syncthreads();

    const float* y0 = depth + n * M + cb * PPB;
    float sums[LSC] = {0.f, 0.f, 0.f, 0.f};
    unsigned cnt = 0;

    #pragma unroll
    for (int it = 0; it < PPT; ++it) {
        float y = __ldg(y0 + it * 256 + t);
        if (y >= 0.001f) {
            cnt++;
            unsigned uy = __float_as_uint(y);
            int b = (int)__fmul_rd(y, (float)NBUCK);   // exact floor for y in [0,1)
            #pragma unroll
            for (int l = 0; l < LSC; l++) {
                const int ln = l * NB + n;
                float4 e = __ldg(&g_lut[ln * NBUCK + b]);
                int j  = (int)__float_as_uint(e.z);
                int j1 = (int)__float_as_uint(e.w);
                float cl = e.x, cr = e.y;
                if (j != j1) {                         // bucket contains centers
                    const float* cc = g_sortedC[ln];
                    float prev = cl, nxt;
                    for (;;) {
                        if (j >= j1) { nxt = (j < P) ? __ldg(cc + j) : 1e18f; break; }
                        float cv = __ldg(cc + j);
                        if (cv > y) { nxt = cv; break; }
                        prev = cv; j++;
                    }
                    cl = prev; cr = nxt;
                }
                float dl = y - cl, dr = cr - y;
                sums[l] += fminf(dl * dl, dr * dr);
                atomicMax(&sMax[l][j], uy);
                atomicMin(&sMin[l][j], uy);
            }
        }
    }

    // cham_y partial sums -> global
    #pragma unroll
    for (int off = 16; off; off >>= 1) {
        #pragma unroll
        for (int l = 0; l < LSC; l++)
            sums[l] += __shfl_down_sync(0xffffffffu, sums[l], off);
        cnt += __shfl_down_sync(0xffffffffu, cnt, off);
    }
    if (lane == 0) {
        #pragma unroll
        for (int l = 0; l < LSC; l++)
            atomicAdd(&g_sumY[l * NB + n], sums[l]);
        atomicAdd(&g_cnt[n], cnt);
    }

    // flush block segment aggregates
    __syncthreads();
    for (int k = t; k < LSC * P1; k += 256) {
        int l = k / P1, i = k - l * P1;
        unsigned um = ((unsigned*)sMax)[k];
        if (um) atomicMax(&g_segMax[l * NB + n][i], um);
        unsigned un = ((unsigned*)sMin)[k];
        if (un != 0x7F800000u) atomicMin(&g_segMin[l * NB + n][i], un);
    }

    // last-block ticket
    __threadfence();
    __syncthreads();
    if (t == 0) {
        unsigned old = atomicAdd(&g_done, 1u);
        sLast = (old == GRID - 1);
    }
    __syncthreads();
    if (!sLast) return;
    __threadfence();

    // ---- finalize: warp w handles ln = w and ln = w+8 ----
    const float NEG = -1e30f;
    const float INF = __uint_as_float(0x7F800000u);
    #pragma unroll
    for (int r = 0; r < 2; r++) {
        int ln = w + r * 8;
        int base = lane * 9;                  // lane covers indices [base, base+9)
        float emx[9], emn[9];
        #pragma unroll
        for (int q = 0; q < 9; q++) {
            int i = base + q;
            if (i < P1) {
                unsigned u = g_segMax[ln][i];
                emx[q] = u ? __uint_as_float(u) : NEG;
                emn[q] = __uint_as_float(g_segMin[ln][i]);
            } else { emx[q] = NEG; emn[q] = INF; }
        }
        // local + warp prefix-max
        float pre[9], run = NEG;
        #pragma unroll
        for (int q = 0; q < 9; q++) { run = fmaxf(run, emx[q]); pre[q] = run; }
        float vmax = run;
        #pragma unroll
        for (int off = 1; off < 32; off <<= 1) {
            float o = __shfl_up_sync(0xffffffffu, vmax, off);
            if (lane >= off) vmax = fmaxf(vmax, o);
        }
        float exL = __shfl_up_sync(0xffffffffu, vmax, 1);
        if (lane == 0) exL = NEG;
        // local + warp suffix-min
        float suf[10], runm = INF;
        #pragma unroll
        for (int q = 8; q >= 0; q--) { runm = fminf(runm, emn[q]); suf[q] = runm; }
        float vmin = runm;
        #pragma unroll
        for (int off = 1; off < 32; off <<= 1) {
            float o = __shfl_down_sync(0xffffffffu, vmin, off);
            if (lane < 32 - off) vmin = fminf(vmin, o);
        }
        float exR = __shfl_down_sync(0xffffffffu, vmin, 1);
        if (lane == 31) exR = INF;
        suf[9] = INF;   // merged with exR below
        // cham_x contributions: center i needs prefmax[0..i], sufmin[i+1..256]
        float s = 0.f;
        #pragma unroll
        for (int q = 0; q < 9; q++) {
            int i = base + q;
            if (i < P) {
                float c  = __ldg(&g_sortedC[ln][i]);
                float pm = fmaxf(pre[q], exL);
                float sm = fminf(suf[q + 1], exR);
                float dl = c - pm;
                float dr = sm - c;
                s += fminf(dl * dl, dr * dr);
            }
        }
        #pragma unroll
        for (int off = 16; off; off >>= 1)
            s += __shfl_down_sync(0xffffffffu, s, off);
        if (lane == 0) chamx[ln] = s * (1.f / P);
    }
    __syncthreads();
    if (t == 0) {
        float loss = 0.f;
        for (int ln = 0; ln < LNN; ln++)
            loss += chamx[ln] + g_sumY[ln] / (float)g_cnt[ln & 3];
        out[0] = loss * (1.f / NB);
    }
}

extern "C" void kernel_launch(void* const* d_in, const int* in_sizes, int n_in,
                              void* d_out, int out_size)
{
    const float* bins  = (const float*)d_in[0];
    const float* depth = (const float*)d_in[1];
    float* out = (float*)d_out;

    k_prep<<<LNN, P>>>(bins);
    k_main<<<GRID, 256>>>(depth, out);
}